// round 17
// baseline (speedup 1.0000x reference)
#include <cuda_runtime.h>
#include <cuda_fp16.h>
#include <cstdint>

#define N_NODES 100000
#define DEG     16
#define E_EDGES (N_NODES * DEG)
#define ALPHA   0.2f
#define N_TILES 782            // ceil(N_NODES/128)
#define GEMM_GRID 296          // 2 CTAs/SM x 148 SMs

// Scratch (static __device__ — no allocs allowed)
__device__ __half  g_h16   [(size_t)N_NODES * 128];  // [h_high(64) | h_low(64)] fp16
__device__ __half  g_hagg16[(size_t)N_NODES * 128];  // [hagg_high | hagg_low]  fp16
__device__ float2  g_ssrc[N_NODES];                  // (ssrc_h, ssrc_l)  fp32
__device__ float2  g_sdst[N_NODES];                  // (sdst_h, sdst_l)  fp32
// W as B-operand [n=128][k=128] fp16, chunk-swizzled (ldmatrix-ready)
__device__ uint32_t g_Wblk[8192];

__device__ __forceinline__ uint32_t sw_off(int row, int k) {
    return (uint32_t)(row * 256 + ((((k >> 3) ^ (row & 7)) << 4) | ((k & 7) << 1)));
}

__device__ __forceinline__ uint32_t smem_u32(const void* p) {
    uint32_t a;
    asm("{ .reg .u64 t; cvta.to.shared.u64 t, %1; cvt.u32.u64 %0, t; }" : "=r"(a) : "l"(p));
    return a;
}

__device__ __forceinline__ void cp_async16(uint32_t smem_dst, const void* gsrc) {
    asm volatile("cp.async.cg.shared.global [%0], [%1], 16;" :: "r"(smem_dst), "l"(gsrc));
}

__device__ __forceinline__ void ldmatrix_x4(uint32_t* r, uint32_t addr) {
    asm volatile("ldmatrix.sync.aligned.m8n8.x4.shared.b16 {%0,%1,%2,%3}, [%4];"
                 : "=r"(r[0]), "=r"(r[1]), "=r"(r[2]), "=r"(r[3]) : "r"(addr));
}

__device__ __forceinline__ void mma_f16(float* c, const uint32_t* a, uint32_t b0, uint32_t b1) {
    asm volatile(
        "mma.sync.aligned.m16n8k16.row.col.f32.f16.f16.f32 "
        "{%0,%1,%2,%3}, {%4,%5,%6,%7}, {%8,%9}, {%0,%1,%2,%3};"
        : "+f"(c[0]), "+f"(c[1]), "+f"(c[2]), "+f"(c[3])
        : "r"(a[0]), "r"(a[1]), "r"(a[2]), "r"(a[3]), "r"(b0), "r"(b1));
}

__device__ __forceinline__ uint32_t f2_to_h2(float2 v) {
    __half2 h = __floats2half2_rn(v.x, v.y);
    return *(uint32_t*)&h;
}

// ---------------------------------------------------------------------------
// K0: bake Wcat as B-operand [n][k] fp16, swizzled. B[n][k] = Wcat[k][n].
// ---------------------------------------------------------------------------
__global__ void k_wprep(const float* __restrict__ Wh, const float* __restrict__ Wl)
{
    int idx = blockIdx.x * blockDim.x + threadIdx.x;
    if (idx >= 128 * 64) return;
    int n = idx >> 6, kp = idx & 63, k = kp * 2;
    const float* Ws = (n < 64) ? Wh : Wl;
    int c = n & 63;
    float w0 = Ws[k * 64 + c];
    float w1 = Ws[(k + 1) * 64 + c];

    __half h0 = __float2half_rn(w0);
    __half h1 = __float2half_rn(w1);
    uint32_t hp = ((uint32_t)__half_as_ushort(h1) << 16) | __half_as_ushort(h0);
    *(uint32_t*)((char*)g_Wblk + sw_off(n, k)) = hp;
}

// ---------------------------------------------------------------------------
// K1: persistent single-pass fp16 mma GEMM. A direct-to-registers, W in 32KB
// smem loaded ONCE per CTA. No per-tile syncthreads (smem read-only after
// the first wait). launch_bounds(256,2): no spills.
// ---------------------------------------------------------------------------
#define SM_TOTAL 32768

__global__ __launch_bounds__(256, 2)
void k_gemm_mma(const float* __restrict__ A,
                const float* __restrict__ ah,
                const float* __restrict__ al)
{
    extern __shared__ char smem[];
    const uint32_t sbase = smem_u32(smem);
    const int tid = threadIdx.x;
    const int wid = tid >> 5;
    const int lane = tid & 31;
    const unsigned FULL = 0xffffffffu;

    // Async W copy (fp16 + swizzled), once per CTA — overlaps first A loads
    {
        const uint4* sw = (const uint4*)g_Wblk;
#pragma unroll
        for (int i = tid; i < 2048; i += 256)
            cp_async16(sbase + i * 16, sw + i);
        asm volatile("cp.async.commit_group;" ::: "memory");
    }

    const int m_base = wid * 16;
    const int cb = (lane & 3) * 2;
    const int g  = lane >> 3;
    const int rr = lane & 7;
    const int b_nof = ((g >> 1) << 3) + rr;
    const int b_kof = (g & 1) << 3;

    bool first = true;

    for (int tile = blockIdx.x; tile < N_TILES; tile += GEMM_GRID) {
        const int rowBase = tile * 128;
        const int row0 = rowBase + m_base + (lane >> 2);
        const bool v0 = row0 < N_NODES;
        const bool v1 = row0 + 8 < N_NODES;
        const float* Ar0 = A + (size_t)row0 * 128;
        const float* Ar1 = Ar0 + 8 * 128;

        // Load A fragments directly into registers
        uint32_t afrag[8][4];
#pragma unroll
        for (int ks = 0; ks < 8; ks++) {
            int k = ks * 16 + cb;
            float2 z = make_float2(0.f, 0.f);
            float2 f0 = v0 ? *(const float2*)(Ar0 + k)     : z;
            float2 f1 = v1 ? *(const float2*)(Ar1 + k)     : z;
            float2 f2 = v0 ? *(const float2*)(Ar0 + k + 8) : z;
            float2 f3 = v1 ? *(const float2*)(Ar1 + k + 8) : z;
            afrag[ks][0] = f2_to_h2(f0);
            afrag[ks][1] = f2_to_h2(f1);
            afrag[ks][2] = f2_to_h2(f2);
            afrag[ks][3] = f2_to_h2(f3);
        }

        if (first) {   // uniform per CTA — safe around __syncthreads
            asm volatile("cp.async.wait_group 0;" ::: "memory");
            __syncthreads();
            first = false;
        }

        float c[16][4];
#pragma unroll
        for (int j = 0; j < 16; j++)
#pragma unroll
            for (int q = 0; q < 4; q++) c[j][q] = 0.f;

#pragma unroll
        for (int ks = 0; ks < 8; ks++) {
            const int kb = ks * 16;
#pragma unroll
            for (int nt = 0; nt < 8; nt++) {
                uint32_t b[4];
                ldmatrix_x4(b, sbase + sw_off(nt * 16 + b_nof, kb + b_kof));
                mma_f16(c[2 * nt],     afrag[ks], b[0], b[1]);
                mma_f16(c[2 * nt + 1], afrag[ks], b[2], b[3]);
            }
        }

        // --- writeout h as fp16 ---
        if (v0) {
            __half* o = g_h16 + (size_t)row0 * 128;
#pragma unroll
            for (int j = 0; j < 16; j++)
                *(__half2*)(o + j * 8 + cb) = __floats2half2_rn(c[j][0], c[j][1]);
        }
        if (v1) {
            __half* o = g_h16 + (size_t)(row0 + 8) * 128;
#pragma unroll
            for (int j = 0; j < 16; j++)
                *(__half2*)(o + j * 8 + cb) = __floats2half2_rn(c[j][2], c[j][3]);
        }

        // --- attention scalars (fp32, from register accumulators) ---
        float ssh0 = 0.f, sdh0 = 0.f, ssl0 = 0.f, sdl0 = 0.f;
        float ssh1 = 0.f, sdh1 = 0.f, ssl1 = 0.f, sdl1 = 0.f;
#pragma unroll
        for (int j = 0; j < 8; j++) {
            int c0 = j * 8 + cb;
            float2 as = *(const float2*)(ah + c0);
            float2 ad = *(const float2*)(ah + 64 + c0);
            ssh0 += c[j][0] * as.x + c[j][1] * as.y;
            sdh0 += c[j][0] * ad.x + c[j][1] * ad.y;
            ssh1 += c[j][2] * as.x + c[j][3] * as.y;
            sdh1 += c[j][2] * ad.x + c[j][3] * ad.y;
        }
#pragma unroll
        for (int j = 8; j < 16; j++) {
            int c0 = (j - 8) * 8 + cb;
            float2 as = *(const float2*)(al + c0);
            float2 ad = *(const float2*)(al + 64 + c0);
            ssl0 += c[j][0] * as.x + c[j][1] * as.y;
            sdl0 += c[j][0] * ad.x + c[j][1] * ad.y;
            ssl1 += c[j][2] * as.x + c[j][3] * as.y;
            sdl1 += c[j][2] * ad.x + c[j][3] * ad.y;
        }
#pragma unroll
        for (int off = 1; off <= 2; off <<= 1) {
            ssh0 += __shfl_xor_sync(FULL, ssh0, off);
            sdh0 += __shfl_xor_sync(FULL, sdh0, off);
            ssl0 += __shfl_xor_sync(FULL, ssl0, off);
            sdl0 += __shfl_xor_sync(FULL, sdl0, off);
            ssh1 += __shfl_xor_sync(FULL, ssh1, off);
            sdh1 += __shfl_xor_sync(FULL, sdh1, off);
            ssl1 += __shfl_xor_sync(FULL, ssl1, off);
            sdl1 += __shfl_xor_sync(FULL, sdl1, off);
        }
        if ((lane & 3) == 0) {
            if (v0) {
                g_ssrc[row0] = make_float2(ssh0, ssl0);
                g_sdst[row0] = make_float2(sdh0, sdl0);
            }
            if (v1) {
                g_ssrc[row0 + 8] = make_float2(ssh1, ssl1);
                g_sdst[row0 + 8] = make_float2(sdh1, sdl1);
            }
        }
    }
}

// ---------------------------------------------------------------------------
// K2: per-node warp aggregation. Self-loop folded; __ldg gathers.
// ---------------------------------------------------------------------------
__global__ __launch_bounds__(256)
void k_agg(const int* __restrict__ dst_arr)
{
    const int warp = (blockIdx.x * blockDim.x + threadIdx.x) >> 5;
    const int lane = threadIdx.x & 31;
    if (warp >= N_NODES) return;
    const int i = warp;
    const unsigned FULL = 0xffffffffu;

    int d = 0;
    if (lane >= 1 && lane < DEG) d = dst_arr[i * DEG + lane];   // edges 1..15

    uint2 sraw = __ldg((const uint2*)(g_h16 + (size_t)i * 128 + lane * 4));
    float2 s0 = __half22float2(*(__half2*)&sraw.x);
    float2 s1 = __half22float2(*(__half2*)&sraw.y);

    __half2 zero = __floats2half2_rn(0.f, 0.f);
    __half2 t0a = zero, t0b = zero, t1a = zero, t1b = zero;
#pragma unroll
    for (int e = 1; e < 8; e++) {
        int de = __shfl_sync(FULL, d, e);
        uint2 raw = __ldg((const uint2*)(g_h16 + (size_t)de * 128 + lane * 4));
        t0a = __hadd2(t0a, *(__half2*)&raw.x);
        t0b = __hadd2(t0b, *(__half2*)&raw.y);
    }
#pragma unroll
    for (int e = 8; e < 16; e++) {
        int de = __shfl_sync(FULL, d, e);
        uint2 raw = __ldg((const uint2*)(g_h16 + (size_t)de * 128 + lane * 4));
        t1a = __hadd2(t1a, *(__half2*)&raw.x);
        t1b = __hadd2(t1b, *(__half2*)&raw.y);
    }
    float2 fa0 = __half22float2(t0a), fa1 = __half22float2(t1a);
    float2 fb0 = __half22float2(t0b), fb1 = __half22float2(t1b);
    float sx = fa0.x + fa1.x, sy = fa0.y + fa1.y;
    float sz = fb0.x + fb1.x, sw = fb0.y + fb1.y;

    float coef = (lane < 16) ? 17.f : 15.f;
    float sgn  = (lane < 16) ? 1.f : -1.f;
    __half2 o0 = __floats2half2_rn(coef * s0.x + sgn * sx, coef * s0.y + sgn * sy);
    __half2 o1 = __floats2half2_rn(coef * s1.x + sgn * sz, coef * s1.y + sgn * sw);
    uint2 ov;
    ov.x = *(uint32_t*)&o0;
    ov.y = *(uint32_t*)&o1;
    *(uint2*)(g_hagg16 + (size_t)i * 128 + lane * 4) = ov;
}

// ---------------------------------------------------------------------------
// K3: weighting + output (fp32 FMA accumulation, dup-lane weights, __ldg)
// ---------------------------------------------------------------------------
__global__ __launch_bounds__(256)
void k_out(const int* __restrict__ dst_arr, float* __restrict__ out)
{
    const int warp = (blockIdx.x * blockDim.x + threadIdx.x) >> 5;
    const int lane = threadIdx.x & 31;
    if (warp >= N_NODES) return;
    const int i = warp;
    const unsigned FULL = 0xffffffffu;

    const int e_idx = lane & 15;
    int d = dst_arr[i * DEG + e_idx];

    float2 si = g_ssrc[i];
    float2 sd = g_sdst[d];

    float s  = (lane < 16) ? (si.x + sd.x) : (si.y + sd.y);
    float lv = s > 0.f ? s : ALPHA * s;
    float eraw = __expf(-lv);

    float r = eraw;
#pragma unroll
    for (int off = 8; off; off >>= 1)
        r += __shfl_xor_sync(FULL, r, off);
    float inv = 1.f / r;

    float q = fminf(eraw, 6.f);
    const int wsel = lane & 16;

    float4 acc = make_float4(0.f, 0.f, 0.f, 0.f);
#pragma unroll
    for (int e = 0; e < DEG; e++) {
        int   de = __shfl_sync(FULL, d, e);
        float w  = __shfl_sync(FULL, q, e + wsel);
        uint2 raw = __ldg((const uint2*)(g_hagg16 + (size_t)de * 128 + lane * 4));
        float2 f0 = __half22float2(*(__half2*)&raw.x);
        float2 f1 = __half22float2(*(__half2*)&raw.y);
        acc.x += w * f0.x; acc.y += w * f0.y;
        acc.z += w * f1.x; acc.w += w * f1.y;
    }

    acc.x *= inv; acc.y *= inv; acc.z *= inv; acc.w *= inv;

    float lx = __shfl_xor_sync(FULL, acc.x, 16);
    float ly = __shfl_xor_sync(FULL, acc.y, 16);
    float lz = __shfl_xor_sync(FULL, acc.z, 16);
    float lw = __shfl_xor_sync(FULL, acc.w, 16);

    if (lane < 16) {
        float4 rv;
        rv.x = 0.5f * (acc.x + lx);
        rv.y = 0.5f * (acc.y + ly);
        rv.z = 0.5f * (acc.z + lz);
        rv.w = 0.5f * (acc.w + lw);
        rv.x = fminf(fmaxf(rv.x, 0.f), 6.f);
        rv.y = fminf(fmaxf(rv.y, 0.f), 6.f);
        rv.z = fminf(fmaxf(rv.z, 0.f), 6.f);
        rv.w = fminf(fmaxf(rv.w, 0.f), 6.f);
        *(float4*)(out + (size_t)i * 64 + lane * 4) = rv;
    }
}

// ---------------------------------------------------------------------------
extern "C" void kernel_launch(void* const* d_in, const int* in_sizes, int n_in,
                              void* d_out, int out_size)
{
    const float* input = (const float*)d_in[0];
    const int*   edge  = (const int*)  d_in[1];
    const float* Wh    = (const float*)d_in[2];
    const float* Wl    = (const float*)d_in[3];
    const float* ah    = (const float*)d_in[4];
    const float* al    = (const float*)d_in[5];
    float* out = (float*)d_out;

    const int* dst = edge + E_EDGES;

    cudaFuncSetAttribute(k_gemm_mma, cudaFuncAttributeMaxDynamicSharedMemorySize, SM_TOTAL);

    k_wprep<<<32, 256>>>(Wh, Wl);

    k_gemm_mma<<<GEMM_GRID, 256, SM_TOTAL>>>(input, ah, al);

    const int warpBlocks = (N_NODES + 7) / 8;
    k_agg<<<warpBlocks, 256>>>(dst);
    k_out<<<warpBlocks, 256>>>(dst, out);
}